// round 8
// baseline (speedup 1.0000x reference)
#include <cuda_runtime.h>
#include <cuda_bf16.h>
#include <math.h>
#include <stdint.h>

#define NN 50000
#define NE 800000
#define NG 256
#define HD 128
#define BN_EPS 1e-5f

// ---------------- device scratch (no allocation allowed) ----------------
__device__ float g_agg[NN * HD];
__device__ float g_x[NN * HD];
__device__ float g_buf[NN * HD];
__device__ float g_enc0[NN * HD];
__device__ float g_enc1[NN * HD];
__device__ float g_stats[4 * 2 * HD];        // 4 slots x (sum[128], sq[128])
__device__ float g_scale[HD];
__device__ float g_shift[HD];
__device__ float g_hg[NG * 2 * HD];
__device__ float g_m1[NG * HD];
__device__ float g_m2[NG * HD];
__device__ __nv_bfloat16 g_wt_hi[8 * HD * HD];   // 8 slots, W^T hi [n][k]
__device__ __nv_bfloat16 g_wt_lo[8 * HD * HD];
// CSR scratch
__device__ int g_deg[NN];
__device__ int g_rowstart[NN + 1];
__device__ int g_cursor[NN];
__device__ int g_eidx0[NE];
__device__ int g_eidx1[NE];

// ---------------- CSR build ----------------
__global__ __launch_bounds__(256) void deg_kernel(const int* __restrict__ dst) {
    int i = blockIdx.x * blockDim.x + threadIdx.x;
    if (i < NE) atomicAdd(&g_deg[dst[i]], 1);
}

__global__ __launch_bounds__(1024) void scan_kernel() {
    __shared__ int ssum[1024];
    int t = threadIdx.x;
    const int CH = (NN + 1023) / 1024;
    int start = t * CH;
    int end = start + CH; if (end > NN) end = NN;
    if (start > NN) start = NN;
    int s = 0;
    for (int i = start; i < end; i++) s += g_deg[i];
    ssum[t] = s;
    __syncthreads();
    for (int off = 1; off < 1024; off <<= 1) {
        int v = (t >= off) ? ssum[t - off] : 0;
        __syncthreads();
        ssum[t] += v;
        __syncthreads();
    }
    int base = (t == 0) ? 0 : ssum[t - 1];
    for (int i = start; i < end; i++) {
        int d = g_deg[i];
        g_rowstart[i] = base;
        g_cursor[i] = base;
        base += d;
    }
    if (t == 1023) g_rowstart[NN] = base;
}

__global__ __launch_bounds__(256) void scatter_kernel(
    const int* __restrict__ src, const int* __restrict__ dst,
    int* __restrict__ eidx)
{
    int i = blockIdx.x * blockDim.x + threadIdx.x;
    if (i < NE) {
        int p = atomicAdd(&g_cursor[dst[i]], 1);
        eidx[p] = src[i];
    }
}

// -------- CSR aggregation ----
__global__ __launch_bounds__(256) void agg_csr_kernel(
    const float* __restrict__ h, const int* __restrict__ eidx,
    const float* __restrict__ eps_ptr, float* __restrict__ xout)
{
    int warp = (blockIdx.x * 256 + threadIdx.x) >> 5;
    int lane = threadIdx.x & 31;
    if (warp >= NN) return;
    int ro = g_rowstart[warp];
    int re = g_rowstart[warp + 1];
    float eps1 = 1.0f + eps_ptr[0];
    float4 hv = ((const float4*)h)[(long long)warp * 32 + lane];
    float4 acc = make_float4(eps1 * hv.x, eps1 * hv.y, eps1 * hv.z, eps1 * hv.w);
    int j = ro;
    for (; j + 4 <= re; j += 4) {
        int s0 = eidx[j], s1 = eidx[j + 1], s2 = eidx[j + 2], s3 = eidx[j + 3];
        float4 v0 = ((const float4*)h)[(long long)s0 * 32 + lane];
        float4 v1 = ((const float4*)h)[(long long)s1 * 32 + lane];
        float4 v2 = ((const float4*)h)[(long long)s2 * 32 + lane];
        float4 v3 = ((const float4*)h)[(long long)s3 * 32 + lane];
        acc.x += v0.x + v1.x + v2.x + v3.x;
        acc.y += v0.y + v1.y + v2.y + v3.y;
        acc.z += v0.z + v1.z + v2.z + v3.z;
        acc.w += v0.w + v1.w + v2.w + v3.w;
    }
    for (; j < re; j++) {
        int s = eidx[j];
        float4 v = ((const float4*)h)[(long long)s * 32 + lane];
        acc.x += v.x; acc.y += v.y; acc.z += v.z; acc.w += v.w;
    }
    ((float4*)xout)[(long long)warp * 32 + lane] = acc;
}

// ================= mma.sync bf16 GEMM machinery =================
#define GSM_TOTAL 131072

__device__ __forceinline__ uint32_t smem_u32(const void* p) {
    uint32_t a;
    asm("{ .reg .u64 t; cvta.to.shared.u64 t, %1; cvt.u32.u64 %0, t; }"
        : "=r"(a) : "l"(p));
    return a;
}
__device__ __forceinline__ uint32_t swz(int row, int k) {
    return (uint32_t)(row * 256 + ((((k >> 3) ^ (row & 7)) & 15) << 4) + (k & 7) * 2);
}
__device__ __forceinline__ unsigned int pack_bf2(float lo, float hi) {
    unsigned int r;
    asm("cvt.rn.bf16x2.f32 %0, %1, %2;" : "=r"(r) : "f"(hi), "f"(lo));
    return r;
}
__device__ __forceinline__ void ldm4(uint32_t* r, uint32_t addr) {
    asm volatile("ldmatrix.sync.aligned.m8n8.x4.shared.b16 {%0,%1,%2,%3}, [%4];"
        : "=r"(r[0]), "=r"(r[1]), "=r"(r[2]), "=r"(r[3]) : "r"(addr));
}
__device__ __forceinline__ void mma16816(float* d, const uint32_t* a,
                                         uint32_t b0, uint32_t b1) {
    asm volatile(
        "mma.sync.aligned.m16n8k16.row.col.f32.bf16.bf16.f32 "
        "{%0,%1,%2,%3}, {%4,%5,%6,%7}, {%8,%9}, {%0,%1,%2,%3};"
        : "+f"(d[0]), "+f"(d[1]), "+f"(d[2]), "+f"(d[3])
        : "r"(a[0]), "r"(a[1]), "r"(a[2]), "r"(a[3]), "r"(b0), "r"(b1));
}

// ---------------- prep: split all 8 weights to bf16 hi/lo + zero stats ----
// slot s<4: Wa[wl=s]; s>=4: Wb[wl=s-4]. wt layout [slot][n][k].
__global__ __launch_bounds__(256) void prep_kernel(
    const float* __restrict__ Wa, const float* __restrict__ Wb)
{
    int idx = blockIdx.x * 256 + threadIdx.x;
    if (idx < 8 * HD * HD) {
        int slot = idx >> 14;
        int m = idx & 16383;
        int k = m >> 7, n = m & 127;
        const float* W = (slot < 4) ? (Wa + slot * HD * HD)
                                    : (Wb + (slot - 4) * HD * HD);
        float v = W[k * HD + n];
        __nv_bfloat16 h = __float2bfloat16(v);
        float r = v - __bfloat162float(h);
        g_wt_hi[slot * HD * HD + n * HD + k] = h;
        g_wt_lo[slot * HD * HD + n * HD + k] = __float2bfloat16(r);
    }
    if (idx < 4 * 2 * HD) g_stats[idx] = 0.f;
}

// ---------------- mma GEMM: out = act(xin') @ W + b, optional fused stats --
__global__ __launch_bounds__(256, 1) void gemm_mma_kernel(
    const float* __restrict__ xin, const float* __restrict__ bias,
    float* __restrict__ out, int wslot, int in_bn, int out_relu, int stat_slot)
{
    extern __shared__ char smem[];
    __shared__ float sbias[HD];
    uint32_t sb = smem_u32(smem);
    int tid = threadIdx.x;
    int row0 = blockIdx.x * 128;

    if (tid < HD) sbias[tid] = bias[tid];

    // ---- stage A (hi/lo split, swizzled) ----
#pragma unroll
    for (int it = 0; it < 8; it++) {
        int idx = tid + it * 256;
        int row = idx >> 4;
        int k0 = (idx & 15) * 8;
        int grow = row0 + row;
        float f[8];
        if (grow < NN) {
            float4 v0 = *(const float4*)&xin[(long long)grow * HD + k0];
            float4 v1 = *(const float4*)&xin[(long long)grow * HD + k0 + 4];
            f[0] = v0.x; f[1] = v0.y; f[2] = v0.z; f[3] = v0.w;
            f[4] = v1.x; f[5] = v1.y; f[6] = v1.z; f[7] = v1.w;
            if (in_bn) {
#pragma unroll
                for (int i = 0; i < 8; i++)
                    f[i] = fmaxf(f[i] * g_scale[k0 + i] + g_shift[k0 + i], 0.f);
            }
        } else {
#pragma unroll
            for (int i = 0; i < 8; i++) f[i] = 0.f;
        }
        float hi[8], lo[8];
#pragma unroll
        for (int i = 0; i < 8; i++) {
            hi[i] = __bfloat162float(__float2bfloat16(f[i]));
            lo[i] = f[i] - hi[i];
        }
        uint4 hv = make_uint4(pack_bf2(hi[0], hi[1]), pack_bf2(hi[2], hi[3]),
                              pack_bf2(hi[4], hi[5]), pack_bf2(hi[6], hi[7]));
        uint4 lv = make_uint4(pack_bf2(lo[0], lo[1]), pack_bf2(lo[2], lo[3]),
                              pack_bf2(lo[4], lo[5]), pack_bf2(lo[6], lo[7]));
        uint32_t off = swz(row, k0);
        *(uint4*)(smem + off) = hv;
        *(uint4*)(smem + 32768 + off) = lv;
    }
    // ---- stage B from preconverted slot ----
    const __nv_bfloat16* wh = g_wt_hi + wslot * HD * HD;
    const __nv_bfloat16* wl_ = g_wt_lo + wslot * HD * HD;
#pragma unroll
    for (int it = 0; it < 8; it++) {
        int idx = tid + it * 256;
        int row = idx >> 4;
        int k0 = (idx & 15) * 8;
        uint4 hv = *(const uint4*)&wh[row * HD + k0];
        uint4 lv = *(const uint4*)&wl_[row * HD + k0];
        uint32_t off = swz(row, k0);
        *(uint4*)(smem + 65536 + off) = hv;
        *(uint4*)(smem + 98304 + off) = lv;
    }
    __syncthreads();

    // ---- mainloop: 4x2 warp grid; warp tile 32 rows x 64 cols ----
    int w = tid >> 5, l = tid & 31;
    int wr = w >> 1, wc = w & 1;
    float acc[2][8][4];
#pragma unroll
    for (int i = 0; i < 2; i++)
#pragma unroll
        for (int nf = 0; nf < 8; nf++)
#pragma unroll
            for (int q = 0; q < 4; q++) acc[i][nf][q] = 0.f;

    int lg8 = ((l >> 3) & 1) * 8 + (l & 7);
    int aKoff = (l >> 4) * 8;
    int bRowL = ((l >> 4) << 3) + (l & 7);
    int bKoff = ((l >> 3) & 1) * 8;

#pragma unroll
    for (int ks = 0; ks < 8; ks++) {
        int k0 = ks * 16;
        uint32_t ah0[4], al0[4], ah1[4], al1[4];
        uint32_t a0 = sb + swz(wr * 32 + lg8, k0 + aKoff);
        uint32_t a1 = sb + swz(wr * 32 + 16 + lg8, k0 + aKoff);
        ldm4(ah0, a0); ldm4(al0, a0 + 32768);
        ldm4(ah1, a1); ldm4(al1, a1 + 32768);
#pragma unroll
        for (int fg = 0; fg < 4; fg++) {
            uint32_t bh[4], bl[4];
            uint32_t ba = sb + 65536 + swz(wc * 64 + 16 * fg + bRowL, k0 + bKoff);
            ldm4(bh, ba); ldm4(bl, ba + 32768);
            // row frag 0
            mma16816(acc[0][2 * fg], ah0, bh[0], bh[1]);
            mma16816(acc[0][2 * fg], al0, bh[0], bh[1]);
            mma16816(acc[0][2 * fg], ah0, bl[0], bl[1]);
            mma16816(acc[0][2 * fg + 1], ah0, bh[2], bh[3]);
            mma16816(acc[0][2 * fg + 1], al0, bh[2], bh[3]);
            mma16816(acc[0][2 * fg + 1], ah0, bl[2], bl[3]);
            // row frag 1
            mma16816(acc[1][2 * fg], ah1, bh[0], bh[1]);
            mma16816(acc[1][2 * fg], al1, bh[0], bh[1]);
            mma16816(acc[1][2 * fg], ah1, bl[0], bl[1]);
            mma16816(acc[1][2 * fg + 1], ah1, bh[2], bh[3]);
            mma16816(acc[1][2 * fg + 1], al1, bh[2], bh[3]);
            mma16816(acc[1][2 * fg + 1], ah1, bl[2], bl[3]);
        }
    }

    // ---- epilogue: bias (+relu), store, optional fused BN stats ----
    int g = l >> 2, t4 = l & 3;
    float colsum[8][2], colsq[8][2];
#pragma unroll
    for (int nf = 0; nf < 8; nf++) {
        colsum[nf][0] = colsum[nf][1] = 0.f;
        colsq[nf][0] = colsq[nf][1] = 0.f;
    }
#pragma unroll
    for (int i = 0; i < 2; i++) {
        int r0 = row0 + wr * 32 + i * 16 + g;
        int r1 = r0 + 8;
#pragma unroll
        for (int nf = 0; nf < 8; nf++) {
            int n = wc * 64 + nf * 8 + 2 * t4;
            float b0 = sbias[n], b1 = sbias[n + 1];
            float o00 = acc[i][nf][0] + b0, o01 = acc[i][nf][1] + b1;
            float o10 = acc[i][nf][2] + b0, o11 = acc[i][nf][3] + b1;
            if (out_relu) {
                o00 = fmaxf(o00, 0.f); o01 = fmaxf(o01, 0.f);
                o10 = fmaxf(o10, 0.f); o11 = fmaxf(o11, 0.f);
            }
            if (r0 < NN) {
                *(float2*)&out[(long long)r0 * HD + n] = make_float2(o00, o01);
                if (stat_slot >= 0) {
                    colsum[nf][0] += o00; colsq[nf][0] += o00 * o00;
                    colsum[nf][1] += o01; colsq[nf][1] += o01 * o01;
                }
            }
            if (r1 < NN) {
                *(float2*)&out[(long long)r1 * HD + n] = make_float2(o10, o11);
                if (stat_slot >= 0) {
                    colsum[nf][0] += o10; colsq[nf][0] += o10 * o10;
                    colsum[nf][1] += o11; colsq[nf][1] += o11 * o11;
                }
            }
        }
    }
    if (stat_slot >= 0) {
        float* st = g_stats + stat_slot * 2 * HD;
#pragma unroll
        for (int nf = 0; nf < 8; nf++) {
#pragma unroll
            for (int j = 0; j < 2; j++) {
#pragma unroll
                for (int m = 4; m < 32; m <<= 1) {
                    colsum[nf][j] += __shfl_xor_sync(0xFFFFFFFFu, colsum[nf][j], m);
                    colsq[nf][j] += __shfl_xor_sync(0xFFFFFFFFu, colsq[nf][j], m);
                }
                if (l < 4) {
                    int n = wc * 64 + nf * 8 + 2 * t4 + j;
                    atomicAdd(&st[n], colsum[nf][j]);
                    atomicAdd(&st[HD + n], colsq[nf][j]);
                }
            }
        }
    }
}

// ---------------- finalize BN stats -> per-channel scale/shift ------------
__global__ void finalize_stats_kernel(const float* __restrict__ gamma,
                                      const float* __restrict__ beta, int slot)
{
    int c = threadIdx.x;
    const float* st = g_stats + slot * 2 * HD;
    const float inv = 1.0f / (float)NN;
    float mean = st[c] * inv;
    float var = st[HD + c] * inv - mean * mean;
    float sc = gamma[c] * rsqrtf(var + BN_EPS);
    g_scale[c] = sc;
    g_shift[c] = beta[c] - mean * sc;
}

// ---------------- per-graph readout (graph_ids sorted) --------------------
__global__ __launch_bounds__(256) void readout_kernel(const int* __restrict__ gids)
{
    int c = threadIdx.x;
    const float* h = (c < HD) ? g_enc0 : g_enc1;
    int cc = c & (HD - 1);
    int n0 = blockIdx.x * 128;
    int n1 = n0 + 128;
    if (n1 > NN) n1 = NN;
    int cur = gids[n0];
    float acc = 0.f;
    for (int n = n0; n < n1; n++) {
        int g = gids[n];
        if (g != cur) {
            atomicAdd(&g_hg[cur * 2 * HD + c], acc);
            acc = 0.f;
            cur = g;
        }
        acc += h[(long long)n * HD + cc];
    }
    atomicAdd(&g_hg[cur * 2 * HD + c], acc);
}

// ---------------- output MLP ----------------
__global__ void mlp1_kernel(const float* __restrict__ W, const float* __restrict__ b)
{
    __shared__ float row[2 * HD];
    int g = blockIdx.x, c = threadIdx.x;
    row[c] = g_hg[g * 2 * HD + c];
    row[c + HD] = g_hg[g * 2 * HD + c + HD];
    __syncthreads();
    float acc = b[c];
#pragma unroll 4
    for (int k = 0; k < 2 * HD; k++) acc = fmaf(row[k], W[k * HD + c], acc);
    g_m1[g * HD + c] = fmaxf(acc, 0.f);
}

__global__ void mlp2_kernel(const float* __restrict__ W, const float* __restrict__ b)
{
    __shared__ float row[HD];
    int g = blockIdx.x, c = threadIdx.x;
    row[c] = g_m1[g * HD + c];
    __syncthreads();
    float acc = b[c];
#pragma unroll 4
    for (int k = 0; k < HD; k++) acc = fmaf(row[k], W[k * HD + c], acc);
    g_m2[g * HD + c] = fmaxf(acc, 0.f);
}

__global__ void mlp3_kernel(const float* __restrict__ W, const float* __restrict__ b,
                            float* __restrict__ out)
{
    int g = threadIdx.x;
    if (g < NG) {
        float acc = b[0];
#pragma unroll 4
        for (int k = 0; k < HD; k++) acc = fmaf(g_m2[g * HD + k], W[k], acc);
        out[g] = acc;
    }
}

// ---------------- launch ----------------
extern "C" void kernel_launch(void* const* d_in, const int* in_sizes, int n_in,
                              void* d_out, int out_size)
{
    const float* feats = (const float*)d_in[0];
    const int* src = (const int*)d_in[1];
    const int* dst = (const int*)d_in[2];
    const int* gids = (const int*)d_in[3];
    const float* eps = (const float*)d_in[5];
    const float* Wa = (const float*)d_in[6];
    const float* ba = (const float*)d_in[7];
    const float* bng = (const float*)d_in[8];
    const float* bnb = (const float*)d_in[9];
    const float* Wb = (const float*)d_in[10];
    const float* bb = (const float*)d_in[11];
    const float* oW1 = (const float*)d_in[12];
    const float* ob1 = (const float*)d_in[13];
    const float* oW2 = (const float*)d_in[14];
    const float* ob2 = (const float*)d_in[15];
    const float* oW3 = (const float*)d_in[16];
    const float* ob3 = (const float*)d_in[17];
    float* out = (float*)d_out;

    cudaFuncSetAttribute(gemm_mma_kernel,
                         cudaFuncAttributeMaxDynamicSharedMemorySize, GSM_TOTAL);

    float *aggp, *xp, *bufp, *e0p, *e1p, *hgp;
    cudaGetSymbolAddress((void**)&aggp, g_agg);
    cudaGetSymbolAddress((void**)&xp, g_x);
    cudaGetSymbolAddress((void**)&bufp, g_buf);
    cudaGetSymbolAddress((void**)&e0p, g_enc0);
    cudaGetSymbolAddress((void**)&e1p, g_enc1);
    cudaGetSymbolAddress((void**)&hgp, g_hg);
    int *ei0p, *ei1p, *degp;
    cudaGetSymbolAddress((void**)&ei0p, g_eidx0);
    cudaGetSymbolAddress((void**)&ei1p, g_eidx1);
    cudaGetSymbolAddress((void**)&degp, g_deg);

    const int gemm_blocks = (NN + 127) / 128;        // 391
    const int edge_blocks = (NE + 255) / 256;        // 3125
    const int agg_blocks = (NN * 32 + 255) / 256;    // 6250

    prep_kernel<<<(8 * HD * HD + 255) / 256, 256>>>(Wa, Wb);

    for (int e = 0; e < 2; e++) {
        int* eidx = e ? ei1p : ei0p;
        cudaMemsetAsync(degp, 0, NN * sizeof(int));
        deg_kernel<<<edge_blocks, 256>>>(dst + (long long)e * NE);
        scan_kernel<<<1, 1024>>>();
        scatter_kernel<<<edge_blocks, 256>>>(src + (long long)e * NE,
                                             dst + (long long)e * NE, eidx);

        float* enc = e ? e1p : e0p;
        const float* hin = feats;
        for (int l = 0; l < 2; l++) {
            int wl = e * 2 + l;
            agg_csr_kernel<<<agg_blocks, 256>>>(hin, eidx, eps + wl, aggp);
            // GEMM1: x = agg @ Wa + ba, fused BN stats into slot wl
            gemm_mma_kernel<<<gemm_blocks, 256, GSM_TOTAL>>>(
                aggp, ba + wl * HD, xp, wl, 0, 0, wl);
            finalize_stats_kernel<<<1, HD>>>(bng + wl * HD, bnb + wl * HD, wl);
            // GEMM2: out = act(relu(BN(x)) @ Wb + bb)
            float* o = (l == 0) ? bufp : enc;
            gemm_mma_kernel<<<gemm_blocks, 256, GSM_TOTAL>>>(
                xp, bb + wl * HD, o, 4 + wl, 1, (l == 0) ? 1 : 0, -1);
            hin = bufp;
        }
    }

    cudaMemsetAsync(hgp, 0, NG * 2 * HD * sizeof(float));
    readout_kernel<<<(NN + 127) / 128, 256>>>(gids);
    mlp1_kernel<<<NG, HD>>>(oW1, ob1);
    mlp2_kernel<<<NG, HD>>>(oW2, ob2);
    mlp3_kernel<<<1, NG>>>(oW3, ob3, out);
}

// round 9
// speedup vs baseline: 1.2701x; 1.2701x over previous
#include <cuda_runtime.h>
#include <cuda_bf16.h>
#include <math.h>
#include <stdint.h>

#define NN 50000
#define NE 800000
#define NG 256
#define HD 128
#define BN_EPS 1e-5f

// ---------------- device scratch (no allocation allowed) ----------------
__device__ float g_agg[NN * HD];
__device__ float g_x[NN * HD];
__device__ float g_buf[NN * HD];
__device__ float g_enc0[NN * HD];
__device__ float g_enc1[NN * HD];
__device__ float g_stats[4 * 2 * HD];        // 4 slots x (sum[128], sq[128])
__device__ float g_scale[HD];
__device__ float g_shift[HD];
__device__ float g_hg[NG * 2 * HD];
__device__ float g_m1[NG * HD];
__device__ float g_m2[NG * HD];
__device__ __nv_bfloat16 g_wt_hi[8 * HD * HD];   // 8 slots, W^T hi [n][k]
__device__ __nv_bfloat16 g_wt_lo[8 * HD * HD];
// CSR scratch (both edge types)
__device__ int g_deg[2 * NN];
__device__ int g_rowstart[2 * (NN + 1)];
__device__ int g_cursor[2 * NN];
__device__ int g_eidx0[NE];
__device__ int g_eidx1[NE];

// ---------------- CSR build (both graphs in one pass) ----------------
__global__ __launch_bounds__(256) void deg2_kernel(const int* __restrict__ dst) {
    int i = blockIdx.x * blockDim.x + threadIdx.x;   // over 2*NE
    if (i < 2 * NE) {
        int e = (i >= NE) ? 1 : 0;
        atomicAdd(&g_deg[e * NN + dst[i]], 1);
    }
}

__global__ __launch_bounds__(1024) void scan2_kernel() {
    __shared__ int ssum[1024];
    int e = blockIdx.x;
    int* deg = g_deg + e * NN;
    int* rowstart = g_rowstart + e * (NN + 1);
    int* cursor = g_cursor + e * NN;
    int t = threadIdx.x;
    const int CH = (NN + 1023) / 1024;
    int start = t * CH;
    int end = start + CH; if (end > NN) end = NN;
    if (start > NN) start = NN;
    int s = 0;
    for (int i = start; i < end; i++) s += deg[i];
    ssum[t] = s;
    __syncthreads();
    for (int off = 1; off < 1024; off <<= 1) {
        int v = (t >= off) ? ssum[t - off] : 0;
        __syncthreads();
        ssum[t] += v;
        __syncthreads();
    }
    int base = (t == 0) ? 0 : ssum[t - 1];
    for (int i = start; i < end; i++) {
        int d = deg[i];
        rowstart[i] = base;
        cursor[i] = base;
        base += d;
    }
    if (t == 1023) rowstart[NN] = base;
}

__global__ __launch_bounds__(256) void scatter2_kernel(
    const int* __restrict__ src, const int* __restrict__ dst)
{
    int i = blockIdx.x * blockDim.x + threadIdx.x;   // over 2*NE
    if (i < 2 * NE) {
        int e = (i >= NE) ? 1 : 0;
        int p = atomicAdd(&g_cursor[e * NN + dst[i]], 1);
        int* eidx = e ? g_eidx1 : g_eidx0;
        eidx[p] = src[i];
    }
}

// -------- CSR aggregation ----
__global__ __launch_bounds__(256) void agg_csr_kernel(
    const float* __restrict__ h, const int* __restrict__ rowstart,
    const int* __restrict__ eidx,
    const float* __restrict__ eps_ptr, float* __restrict__ xout)
{
    int warp = (blockIdx.x * 256 + threadIdx.x) >> 5;
    int lane = threadIdx.x & 31;
    if (warp >= NN) return;
    int ro = rowstart[warp];
    int re = rowstart[warp + 1];
    float eps1 = 1.0f + eps_ptr[0];
    float4 hv = ((const float4*)h)[(long long)warp * 32 + lane];
    float4 acc = make_float4(eps1 * hv.x, eps1 * hv.y, eps1 * hv.z, eps1 * hv.w);
    int j = ro;
    for (; j + 4 <= re; j += 4) {
        int s0 = eidx[j], s1 = eidx[j + 1], s2 = eidx[j + 2], s3 = eidx[j + 3];
        float4 v0 = ((const float4*)h)[(long long)s0 * 32 + lane];
        float4 v1 = ((const float4*)h)[(long long)s1 * 32 + lane];
        float4 v2 = ((const float4*)h)[(long long)s2 * 32 + lane];
        float4 v3 = ((const float4*)h)[(long long)s3 * 32 + lane];
        acc.x += v0.x + v1.x + v2.x + v3.x;
        acc.y += v0.y + v1.y + v2.y + v3.y;
        acc.z += v0.z + v1.z + v2.z + v3.z;
        acc.w += v0.w + v1.w + v2.w + v3.w;
    }
    for (; j < re; j++) {
        int s = eidx[j];
        float4 v = ((const float4*)h)[(long long)s * 32 + lane];
        acc.x += v.x; acc.y += v.y; acc.z += v.z; acc.w += v.w;
    }
    ((float4*)xout)[(long long)warp * 32 + lane] = acc;
}

// ================= mma.sync bf16 GEMM machinery =================
#define GSM_TOTAL 131072

__device__ __forceinline__ uint32_t smem_u32(const void* p) {
    uint32_t a;
    asm("{ .reg .u64 t; cvta.to.shared.u64 t, %1; cvt.u32.u64 %0, t; }"
        : "=r"(a) : "l"(p));
    return a;
}
__device__ __forceinline__ uint32_t swz(int row, int k) {
    return (uint32_t)(row * 256 + ((((k >> 3) ^ (row & 7)) & 15) << 4) + (k & 7) * 2);
}
__device__ __forceinline__ unsigned int pack_bf2(float lo, float hi) {
    unsigned int r;
    asm("cvt.rn.bf16x2.f32 %0, %1, %2;" : "=r"(r) : "f"(hi), "f"(lo));
    return r;
}
__device__ __forceinline__ void ldm4(uint32_t* r, uint32_t addr) {
    asm volatile("ldmatrix.sync.aligned.m8n8.x4.shared.b16 {%0,%1,%2,%3}, [%4];"
        : "=r"(r[0]), "=r"(r[1]), "=r"(r[2]), "=r"(r[3]) : "r"(addr));
}
__device__ __forceinline__ void mma16816(float* d, const uint32_t* a,
                                         uint32_t b0, uint32_t b1) {
    asm volatile(
        "mma.sync.aligned.m16n8k16.row.col.f32.bf16.bf16.f32 "
        "{%0,%1,%2,%3}, {%4,%5,%6,%7}, {%8,%9}, {%0,%1,%2,%3};"
        : "+f"(d[0]), "+f"(d[1]), "+f"(d[2]), "+f"(d[3])
        : "r"(a[0]), "r"(a[1]), "r"(a[2]), "r"(a[3]), "r"(b0), "r"(b1));
}

// ---------------- prep: split all 8 weights to bf16 hi/lo + zero stats ----
__global__ __launch_bounds__(256) void prep_kernel(
    const float* __restrict__ Wa, const float* __restrict__ Wb)
{
    int idx = blockIdx.x * 256 + threadIdx.x;
    if (idx < 8 * HD * HD) {
        int slot = idx >> 14;
        int m = idx & 16383;
        int k = m >> 7, n = m & 127;
        const float* W = (slot < 4) ? (Wa + slot * HD * HD)
                                    : (Wb + (slot - 4) * HD * HD);
        float v = W[k * HD + n];
        __nv_bfloat16 h = __float2bfloat16(v);
        float r = v - __bfloat162float(h);
        g_wt_hi[slot * HD * HD + n * HD + k] = h;
        g_wt_lo[slot * HD * HD + n * HD + k] = __float2bfloat16(r);
    }
    if (idx < 4 * 2 * HD) g_stats[idx] = 0.f;
}

// ---------------- mma GEMM: out = act(xin') @ W + b ------------------
// Round-7 shape: warp owns 16 rows x 128 cols. No fused stats.
__global__ __launch_bounds__(256, 1) void gemm_mma_kernel(
    const float* __restrict__ xin, const float* __restrict__ bias,
    float* __restrict__ out, int wslot, int in_bn, int out_relu)
{
    extern __shared__ char smem[];
    __shared__ float sbias[HD];
    uint32_t sb = smem_u32(smem);
    int tid = threadIdx.x;
    int row0 = blockIdx.x * 128;

    if (tid < HD) sbias[tid] = bias[tid];

    // ---- stage A (hi/lo split, swizzled) ----
#pragma unroll
    for (int it = 0; it < 8; it++) {
        int idx = tid + it * 256;
        int row = idx >> 4;
        int k0 = (idx & 15) * 8;
        int grow = row0 + row;
        float f[8];
        if (grow < NN) {
            float4 v0 = *(const float4*)&xin[(long long)grow * HD + k0];
            float4 v1 = *(const float4*)&xin[(long long)grow * HD + k0 + 4];
            f[0] = v0.x; f[1] = v0.y; f[2] = v0.z; f[3] = v0.w;
            f[4] = v1.x; f[5] = v1.y; f[6] = v1.z; f[7] = v1.w;
            if (in_bn) {
#pragma unroll
                for (int i = 0; i < 8; i++)
                    f[i] = fmaxf(f[i] * g_scale[k0 + i] + g_shift[k0 + i], 0.f);
            }
        } else {
#pragma unroll
            for (int i = 0; i < 8; i++) f[i] = 0.f;
        }
        float hi[8], lo[8];
#pragma unroll
        for (int i = 0; i < 8; i++) {
            hi[i] = __bfloat162float(__float2bfloat16(f[i]));
            lo[i] = f[i] - hi[i];
        }
        uint4 hv = make_uint4(pack_bf2(hi[0], hi[1]), pack_bf2(hi[2], hi[3]),
                              pack_bf2(hi[4], hi[5]), pack_bf2(hi[6], hi[7]));
        uint4 lv = make_uint4(pack_bf2(lo[0], lo[1]), pack_bf2(lo[2], lo[3]),
                              pack_bf2(lo[4], lo[5]), pack_bf2(lo[6], lo[7]));
        uint32_t off = swz(row, k0);
        *(uint4*)(smem + off) = hv;
        *(uint4*)(smem + 32768 + off) = lv;
    }
    // ---- stage B from preconverted slot ----
    const __nv_bfloat16* wh = g_wt_hi + wslot * HD * HD;
    const __nv_bfloat16* wl_ = g_wt_lo + wslot * HD * HD;
#pragma unroll
    for (int it = 0; it < 8; it++) {
        int idx = tid + it * 256;
        int row = idx >> 4;
        int k0 = (idx & 15) * 8;
        uint4 hv = *(const uint4*)&wh[row * HD + k0];
        uint4 lv = *(const uint4*)&wl_[row * HD + k0];
        uint32_t off = swz(row, k0);
        *(uint4*)(smem + 65536 + off) = hv;
        *(uint4*)(smem + 98304 + off) = lv;
    }
    __syncthreads();

    // ---- mainloop: warp w owns rows 16w..16w+15, all 128 cols ----
    int w = tid >> 5, l = tid & 31;
    float acc[16][4];
#pragma unroll
    for (int f = 0; f < 16; f++)
#pragma unroll
        for (int q = 0; q < 4; q++) acc[f][q] = 0.f;

    int rowA = 16 * w + ((l >> 3) & 1) * 8 + (l & 7);
    int aKoff = (l >> 4) * 8;
    int bRowL = ((l >> 4) << 3) + (l & 7);
    int bKoff = ((l >> 3) & 1) * 8;

#pragma unroll
    for (int ks = 0; ks < 8; ks++) {
        int k0 = ks * 16;
        uint32_t ah[4], al[4];
        uint32_t aaddr = sb + swz(rowA, k0 + aKoff);
        ldm4(ah, aaddr);
        ldm4(al, aaddr + 32768);
#pragma unroll
        for (int fg = 0; fg < 8; fg++) {
            uint32_t bh[4], bl[4];
            uint32_t baddr = sb + 65536 + swz(16 * fg + bRowL, k0 + bKoff);
            ldm4(bh, baddr);
            ldm4(bl, baddr + 32768);
            mma16816(acc[2 * fg], ah, bh[0], bh[1]);
            mma16816(acc[2 * fg], al, bh[0], bh[1]);
            mma16816(acc[2 * fg], ah, bl[0], bl[1]);
            mma16816(acc[2 * fg + 1], ah, bh[2], bh[3]);
            mma16816(acc[2 * fg + 1], al, bh[2], bh[3]);
            mma16816(acc[2 * fg + 1], ah, bl[2], bl[3]);
        }
    }

    // ---- epilogue: bias (+relu), store ----
    int g = l >> 2, t4 = l & 3;
    int r0 = row0 + 16 * w + g;
    int r1 = r0 + 8;
#pragma unroll
    for (int f = 0; f < 16; f++) {
        int n = 8 * f + 2 * t4;
        float b0 = sbias[n], b1 = sbias[n + 1];
        float o00 = acc[f][0] + b0, o01 = acc[f][1] + b1;
        float o10 = acc[f][2] + b0, o11 = acc[f][3] + b1;
        if (out_relu) {
            o00 = fmaxf(o00, 0.f); o01 = fmaxf(o01, 0.f);
            o10 = fmaxf(o10, 0.f); o11 = fmaxf(o11, 0.f);
        }
        if (r0 < NN) {
            *(float2*)&out[(long long)r0 * HD + n] = make_float2(o00, o01);
        }
        if (r1 < NN) {
            *(float2*)&out[(long long)r1 * HD + n] = make_float2(o10, o11);
        }
    }
}

// ---------------- BN column stats over g_x (into slot) ----------------
__global__ __launch_bounds__(256) void stats_kernel(const float* __restrict__ x,
                                                    int slot) {
    __shared__ float ss[256], sq[256];
    float* st = g_stats + slot * 2 * HD;
    int tid = threadIdx.x;
    int col = tid & 127;
    int half = tid >> 7;
    int r0 = blockIdx.x * 128 + half * 64;
    float s = 0.f, q = 0.f;
    for (int i = 0; i < 64; i++) {
        int r = r0 + i;
        if (r < NN) {
            float v = x[(long long)r * HD + col];
            s += v;
            q += v * v;
        }
    }
    ss[tid] = s; sq[tid] = q;
    __syncthreads();
    if (half == 0) {
        s += ss[tid + 128];
        q += sq[tid + 128];
        atomicAdd(&st[col], s);
        atomicAdd(&st[HD + col], q);
    }
}

// ---------------- finalize BN stats -> per-channel scale/shift ------------
__global__ void finalize_stats_kernel(const float* __restrict__ gamma,
                                      const float* __restrict__ beta, int slot)
{
    int c = threadIdx.x;
    const float* st = g_stats + slot * 2 * HD;
    const float inv = 1.0f / (float)NN;
    float mean = st[c] * inv;
    float var = st[HD + c] * inv - mean * mean;
    float sc = gamma[c] * rsqrtf(var + BN_EPS);
    g_scale[c] = sc;
    g_shift[c] = beta[c] - mean * sc;
}

// ---------------- per-graph readout (graph_ids sorted) --------------------
__global__ __launch_bounds__(256) void readout_kernel(const int* __restrict__ gids)
{
    int c = threadIdx.x;
    const float* h = (c < HD) ? g_enc0 : g_enc1;
    int cc = c & (HD - 1);
    int n0 = blockIdx.x * 128;
    int n1 = n0 + 128;
    if (n1 > NN) n1 = NN;
    int cur = gids[n0];
    float acc = 0.f;
    for (int n = n0; n < n1; n++) {
        int g = gids[n];
        if (g != cur) {
            atomicAdd(&g_hg[cur * 2 * HD + c], acc);
            acc = 0.f;
            cur = g;
        }
        acc += h[(long long)n * HD + cc];
    }
    atomicAdd(&g_hg[cur * 2 * HD + c], acc);
}

// ---------------- output MLP ----------------
__global__ void mlp1_kernel(const float* __restrict__ W, const float* __restrict__ b)
{
    __shared__ float row[2 * HD];
    int g = blockIdx.x, c = threadIdx.x;
    row[c] = g_hg[g * 2 * HD + c];
    row[c + HD] = g_hg[g * 2 * HD + c + HD];
    __syncthreads();
    float acc = b[c];
#pragma unroll 4
    for (int k = 0; k < 2 * HD; k++) acc = fmaf(row[k], W[k * HD + c], acc);
    g_m1[g * HD + c] = fmaxf(acc, 0.f);
}

__global__ void mlp2_kernel(const float* __restrict__ W, const float* __restrict__ b)
{
    __shared__ float row[HD];
    int g = blockIdx.x, c = threadIdx.x;
    row[c] = g_m1[g * HD + c];
    __syncthreads();
    float acc = b[c];
#pragma unroll 4
    for (int k = 0; k < HD; k++) acc = fmaf(row[k], W[k * HD + c], acc);
    g_m2[g * HD + c] = fmaxf(acc, 0.f);
}

__global__ void mlp3_kernel(const float* __restrict__ W, const float* __restrict__ b,
                            float* __restrict__ out)
{
    int g = threadIdx.x;
    if (g < NG) {
        float acc = b[0];
#pragma unroll 4
        for (int k = 0; k < HD; k++) acc = fmaf(g_m2[g * HD + k], W[k], acc);
        out[g] = acc;
    }
}

// ---------------- launch ----------------
extern "C" void kernel_launch(void* const* d_in, const int* in_sizes, int n_in,
                              void* d_out, int out_size)
{
    const float* feats = (const float*)d_in[0];
    const int* src = (const int*)d_in[1];
    const int* dst = (const int*)d_in[2];
    const int* gids = (const int*)d_in[3];
    const float* eps = (const float*)d_in[5];
    const float* Wa = (const float*)d_in[6];
    const float* ba = (const float*)d_in[7];
    const float* bng = (const float*)d_in[8];
    const float* bnb = (const float*)d_in[9];
    const float* Wb = (const float*)d_in[10];
    const float* bb = (const float*)d_in[11];
    const float* oW1 = (const float*)d_in[12];
    const float* ob1 = (const float*)d_in[13];
    const float* oW2 = (const float*)d_in[14];
    const float* ob2 = (const float*)d_in[15];
    const float* oW3 = (const float*)d_in[16];
    const float* ob3 = (const float*)d_in[17];
    float* out = (float*)d_out;

    cudaFuncSetAttribute(gemm_mma_kernel,
                         cudaFuncAttributeMaxDynamicSharedMemorySize, GSM_TOTAL);

    float *aggp, *xp, *bufp, *e0p, *e1p, *hgp;
    cudaGetSymbolAddress((void**)&aggp, g_agg);
    cudaGetSymbolAddress((void**)&xp, g_x);
    cudaGetSymbolAddress((void**)&bufp, g_buf);
    cudaGetSymbolAddress((void**)&e0p, g_enc0);
    cudaGetSymbolAddress((void**)&e1p, g_enc1);
    cudaGetSymbolAddress((void**)&hgp, g_hg);
    int *ei0p, *ei1p, *degp, *rsp;
    cudaGetSymbolAddress((void**)&ei0p, g_eidx0);
    cudaGetSymbolAddress((void**)&ei1p, g_eidx1);
    cudaGetSymbolAddress((void**)&degp, g_deg);
    cudaGetSymbolAddress((void**)&rsp, g_rowstart);

    const int gemm_blocks = (NN + 127) / 128;        // 391
    const int edge2_blocks = (2 * NE + 255) / 256;   // 6250
    const int agg_blocks = (NN * 32 + 255) / 256;    // 6250

    // Prep: weight split + stats zero; CSR for both edge lists in one pass
    prep_kernel<<<(8 * HD * HD + 255) / 256, 256>>>(Wa, Wb);
    cudaMemsetAsync(degp, 0, 2 * NN * sizeof(int));
    deg2_kernel<<<edge2_blocks, 256>>>(dst);
    scan2_kernel<<<2, 1024>>>();
    scatter2_kernel<<<edge2_blocks, 256>>>(src, dst);

    for (int e = 0; e < 2; e++) {
        int* eidx = e ? ei1p : ei0p;
        const int* rowstart = rsp + e * (NN + 1);
        float* enc = e ? e1p : e0p;
        const float* hin = feats;
        for (int l = 0; l < 2; l++) {
            int wl = e * 2 + l;
            agg_csr_kernel<<<agg_blocks, 256>>>(hin, rowstart, eidx, eps + wl, aggp);
            // GEMM1: x = agg @ Wa + ba
            gemm_mma_kernel<<<gemm_blocks, 256, GSM_TOTAL>>>(
                aggp, ba + wl * HD, xp, wl, 0, 0);
            // BN stats (slot pre-zeroed by prep)
            stats_kernel<<<gemm_blocks, 256>>>(xp, wl);
            finalize_stats_kernel<<<1, HD>>>(bng + wl * HD, bnb + wl * HD, wl);
            // GEMM2: out = act(relu(BN(x)) @ Wb + bb)
            float* o = (l == 0) ? bufp : enc;
            gemm_mma_kernel<<<gemm_blocks, 256, GSM_TOTAL>>>(
                xp, bb + wl * HD, o, 4 + wl, 1, (l == 0) ? 1 : 0);
            hin = bufp;
        }
    }

    cudaMemsetAsync(hgp, 0, NG * 2 * HD * sizeof(float));
    readout_kernel<<<(NN + 127) / 128, 256>>>(gids);
    mlp1_kernel<<<NG, HD>>>(oW1, ob1);
    mlp2_kernel<<<NG, HD>>>(oW2, ob2);
    mlp3_kernel<<<1, NG>>>(oW3, ob3, out);
}

// round 10
// speedup vs baseline: 1.3834x; 1.0892x over previous
#include <cuda_runtime.h>
#include <cuda_bf16.h>
#include <math.h>
#include <stdint.h>

#define NN 50000
#define NE 800000
#define NG 256
#define HD 128
#define BN_EPS 1e-5f

// ---------------- device scratch (no allocation allowed) ----------------
// per-encoder chain buffers (stream-parallel chains must not share)
__device__ float g_agg0[NN * HD];
__device__ float g_agg1[NN * HD];
__device__ float g_x0[NN * HD];
__device__ float g_x1[NN * HD];
__device__ float g_buf0[NN * HD];
__device__ float g_buf1[NN * HD];
__device__ float g_enc0[NN * HD];
__device__ float g_enc1[NN * HD];
__device__ float g_stats[4 * 2 * HD];        // 4 slots x (sum[128], sq[128])
__device__ float g_scale[4 * HD];            // slot-indexed
__device__ float g_shift[4 * HD];
__device__ float g_hg[NG * 2 * HD];
__device__ float g_m1[NG * HD];
__device__ float g_m2[NG * HD];
__device__ __nv_bfloat16 g_wt_hi[8 * HD * HD];   // 8 slots, W^T hi [n][k]
__device__ __nv_bfloat16 g_wt_lo[8 * HD * HD];
// CSR scratch (both edge types)
__device__ int g_deg[2 * NN];
__device__ int g_rowstart[2 * (NN + 1)];
__device__ int g_cursor[2 * NN];
__device__ int g_eidx0[NE];
__device__ int g_eidx1[NE];

// ---------------- CSR build (both graphs in one pass) ----------------
__global__ __launch_bounds__(256) void deg2_kernel(const int* __restrict__ dst) {
    int i = blockIdx.x * blockDim.x + threadIdx.x;   // over 2*NE
    if (i < 2 * NE) {
        int e = (i >= NE) ? 1 : 0;
        atomicAdd(&g_deg[e * NN + dst[i]], 1);
    }
}

__global__ __launch_bounds__(1024) void scan2_kernel() {
    __shared__ int ssum[1024];
    int e = blockIdx.x;
    int* deg = g_deg + e * NN;
    int* rowstart = g_rowstart + e * (NN + 1);
    int* cursor = g_cursor + e * NN;
    int t = threadIdx.x;
    const int CH = (NN + 1023) / 1024;
    int start = t * CH;
    int end = start + CH; if (end > NN) end = NN;
    if (start > NN) start = NN;
    int s = 0;
    for (int i = start; i < end; i++) s += deg[i];
    ssum[t] = s;
    __syncthreads();
    for (int off = 1; off < 1024; off <<= 1) {
        int v = (t >= off) ? ssum[t - off] : 0;
        __syncthreads();
        ssum[t] += v;
        __syncthreads();
    }
    int base = (t == 0) ? 0 : ssum[t - 1];
    for (int i = start; i < end; i++) {
        int d = deg[i];
        rowstart[i] = base;
        cursor[i] = base;
        base += d;
    }
    if (t == 1023) rowstart[NN] = base;
}

__global__ __launch_bounds__(256) void scatter2_kernel(
    const int* __restrict__ src, const int* __restrict__ dst)
{
    int i = blockIdx.x * blockDim.x + threadIdx.x;   // over 2*NE
    if (i < 2 * NE) {
        int e = (i >= NE) ? 1 : 0;
        int p = atomicAdd(&g_cursor[e * NN + dst[i]], 1);
        int* eidx = e ? g_eidx1 : g_eidx0;
        eidx[p] = src[i];
    }
}

// -------- CSR aggregation ----
__global__ __launch_bounds__(256) void agg_csr_kernel(
    const float* __restrict__ h, const int* __restrict__ rowstart,
    const int* __restrict__ eidx,
    const float* __restrict__ eps_ptr, float* __restrict__ xout)
{
    int warp = (blockIdx.x * 256 + threadIdx.x) >> 5;
    int lane = threadIdx.x & 31;
    if (warp >= NN) return;
    int ro = rowstart[warp];
    int re = rowstart[warp + 1];
    float eps1 = 1.0f + eps_ptr[0];
    float4 hv = ((const float4*)h)[(long long)warp * 32 + lane];
    float4 acc = make_float4(eps1 * hv.x, eps1 * hv.y, eps1 * hv.z, eps1 * hv.w);
    int j = ro;
    for (; j + 4 <= re; j += 4) {
        int s0 = eidx[j], s1 = eidx[j + 1], s2 = eidx[j + 2], s3 = eidx[j + 3];
        float4 v0 = ((const float4*)h)[(long long)s0 * 32 + lane];
        float4 v1 = ((const float4*)h)[(long long)s1 * 32 + lane];
        float4 v2 = ((const float4*)h)[(long long)s2 * 32 + lane];
        float4 v3 = ((const float4*)h)[(long long)s3 * 32 + lane];
        acc.x += v0.x + v1.x + v2.x + v3.x;
        acc.y += v0.y + v1.y + v2.y + v3.y;
        acc.z += v0.z + v1.z + v2.z + v3.z;
        acc.w += v0.w + v1.w + v2.w + v3.w;
    }
    for (; j < re; j++) {
        int s = eidx[j];
        float4 v = ((const float4*)h)[(long long)s * 32 + lane];
        acc.x += v.x; acc.y += v.y; acc.z += v.z; acc.w += v.w;
    }
    ((float4*)xout)[(long long)warp * 32 + lane] = acc;
}

// ================= mma.sync bf16 GEMM machinery =================
#define GSM_TOTAL 131072

__device__ __forceinline__ uint32_t smem_u32(const void* p) {
    uint32_t a;
    asm("{ .reg .u64 t; cvta.to.shared.u64 t, %1; cvt.u32.u64 %0, t; }"
        : "=r"(a) : "l"(p));
    return a;
}
__device__ __forceinline__ uint32_t swz(int row, int k) {
    return (uint32_t)(row * 256 + ((((k >> 3) ^ (row & 7)) & 15) << 4) + (k & 7) * 2);
}
__device__ __forceinline__ unsigned int pack_bf2(float lo, float hi) {
    unsigned int r;
    asm("cvt.rn.bf16x2.f32 %0, %1, %2;" : "=r"(r) : "f"(hi), "f"(lo));
    return r;
}
__device__ __forceinline__ void ldm4(uint32_t* r, uint32_t addr) {
    asm volatile("ldmatrix.sync.aligned.m8n8.x4.shared.b16 {%0,%1,%2,%3}, [%4];"
        : "=r"(r[0]), "=r"(r[1]), "=r"(r[2]), "=r"(r[3]) : "r"(addr));
}
__device__ __forceinline__ void mma16816(float* d, const uint32_t* a,
                                         uint32_t b0, uint32_t b1) {
    asm volatile(
        "mma.sync.aligned.m16n8k16.row.col.f32.bf16.bf16.f32 "
        "{%0,%1,%2,%3}, {%4,%5,%6,%7}, {%8,%9}, {%0,%1,%2,%3};"
        : "+f"(d[0]), "+f"(d[1]), "+f"(d[2]), "+f"(d[3])
        : "r"(a[0]), "r"(a[1]), "r"(a[2]), "r"(a[3]), "r"(b0), "r"(b1));
}

// ---------------- prep: split all 8 weights to bf16 hi/lo + zero stats ----
__global__ __launch_bounds__(256) void prep_kernel(
    const float* __restrict__ Wa, const float* __restrict__ Wb)
{
    int idx = blockIdx.x * 256 + threadIdx.x;
    if (idx < 8 * HD * HD) {
        int slot = idx >> 14;
        int m = idx & 16383;
        int k = m >> 7, n = m & 127;
        const float* W = (slot < 4) ? (Wa + slot * HD * HD)
                                    : (Wb + (slot - 4) * HD * HD);
        float v = W[k * HD + n];
        __nv_bfloat16 h = __float2bfloat16(v);
        float r = v - __bfloat162float(h);
        g_wt_hi[slot * HD * HD + n * HD + k] = h;
        g_wt_lo[slot * HD * HD + n * HD + k] = __float2bfloat16(r);
    }
    if (idx < 4 * 2 * HD) g_stats[idx] = 0.f;
}

// ---------------- mma GEMM: out = act(xin') @ W + b ------------------
// bn_slot >= 0: xin' = relu(xin*scale[slot]+shift[slot]); else xin' = xin.
__global__ __launch_bounds__(256, 1) void gemm_mma_kernel(
    const float* __restrict__ xin, const float* __restrict__ bias,
    float* __restrict__ out, int wslot, int bn_slot, int out_relu)
{
    extern __shared__ char smem[];
    __shared__ float sbias[HD];
    uint32_t sb = smem_u32(smem);
    int tid = threadIdx.x;
    int row0 = blockIdx.x * 128;

    if (tid < HD) sbias[tid] = bias[tid];
    const float* bscale = g_scale + (bn_slot < 0 ? 0 : bn_slot) * HD;
    const float* bshift = g_shift + (bn_slot < 0 ? 0 : bn_slot) * HD;

    // ---- stage A (hi/lo split, swizzled) ----
#pragma unroll
    for (int it = 0; it < 8; it++) {
        int idx = tid + it * 256;
        int row = idx >> 4;
        int k0 = (idx & 15) * 8;
        int grow = row0 + row;
        float f[8];
        if (grow < NN) {
            float4 v0 = *(const float4*)&xin[(long long)grow * HD + k0];
            float4 v1 = *(const float4*)&xin[(long long)grow * HD + k0 + 4];
            f[0] = v0.x; f[1] = v0.y; f[2] = v0.z; f[3] = v0.w;
            f[4] = v1.x; f[5] = v1.y; f[6] = v1.z; f[7] = v1.w;
            if (bn_slot >= 0) {
#pragma unroll
                for (int i = 0; i < 8; i++)
                    f[i] = fmaxf(f[i] * bscale[k0 + i] + bshift[k0 + i], 0.f);
            }
        } else {
#pragma unroll
            for (int i = 0; i < 8; i++) f[i] = 0.f;
        }
        float hi[8], lo[8];
#pragma unroll
        for (int i = 0; i < 8; i++) {
            hi[i] = __bfloat162float(__float2bfloat16(f[i]));
            lo[i] = f[i] - hi[i];
        }
        uint4 hv = make_uint4(pack_bf2(hi[0], hi[1]), pack_bf2(hi[2], hi[3]),
                              pack_bf2(hi[4], hi[5]), pack_bf2(hi[6], hi[7]));
        uint4 lv = make_uint4(pack_bf2(lo[0], lo[1]), pack_bf2(lo[2], lo[3]),
                              pack_bf2(lo[4], lo[5]), pack_bf2(lo[6], lo[7]));
        uint32_t off = swz(row, k0);
        *(uint4*)(smem + off) = hv;
        *(uint4*)(smem + 32768 + off) = lv;
    }
    // ---- stage B from preconverted slot ----
    const __nv_bfloat16* wh = g_wt_hi + wslot * HD * HD;
    const __nv_bfloat16* wl_ = g_wt_lo + wslot * HD * HD;
#pragma unroll
    for (int it = 0; it < 8; it++) {
        int idx = tid + it * 256;
        int row = idx >> 4;
        int k0 = (idx & 15) * 8;
        uint4 hv = *(const uint4*)&wh[row * HD + k0];
        uint4 lv = *(const uint4*)&wl_[row * HD + k0];
        uint32_t off = swz(row, k0);
        *(uint4*)(smem + 65536 + off) = hv;
        *(uint4*)(smem + 98304 + off) = lv;
    }
    __syncthreads();

    // ---- mainloop: warp w owns rows 16w..16w+15, all 128 cols ----
    int w = tid >> 5, l = tid & 31;
    float acc[16][4];
#pragma unroll
    for (int f = 0; f < 16; f++)
#pragma unroll
        for (int q = 0; q < 4; q++) acc[f][q] = 0.f;

    int rowA = 16 * w + ((l >> 3) & 1) * 8 + (l & 7);
    int aKoff = (l >> 4) * 8;
    int bRowL = ((l >> 4) << 3) + (l & 7);
    int bKoff = ((l >> 3) & 1) * 8;

#pragma unroll
    for (int ks = 0; ks < 8; ks++) {
        int k0 = ks * 16;
        uint32_t ah[4], al[4];
        uint32_t aaddr = sb + swz(rowA, k0 + aKoff);
        ldm4(ah, aaddr);
        ldm4(al, aaddr + 32768);
#pragma unroll
        for (int fg = 0; fg < 8; fg++) {
            uint32_t bh[4], bl[4];
            uint32_t baddr = sb + 65536 + swz(16 * fg + bRowL, k0 + bKoff);
            ldm4(bh, baddr);
            ldm4(bl, baddr + 32768);
            mma16816(acc[2 * fg], ah, bh[0], bh[1]);
            mma16816(acc[2 * fg], al, bh[0], bh[1]);
            mma16816(acc[2 * fg], ah, bl[0], bl[1]);
            mma16816(acc[2 * fg + 1], ah, bh[2], bh[3]);
            mma16816(acc[2 * fg + 1], al, bh[2], bh[3]);
            mma16816(acc[2 * fg + 1], ah, bl[2], bl[3]);
        }
    }

    // ---- epilogue: bias (+relu), store ----
    int g = l >> 2, t4 = l & 3;
    int r0 = row0 + 16 * w + g;
    int r1 = r0 + 8;
#pragma unroll
    for (int f = 0; f < 16; f++) {
        int n = 8 * f + 2 * t4;
        float b0 = sbias[n], b1 = sbias[n + 1];
        float o00 = acc[f][0] + b0, o01 = acc[f][1] + b1;
        float o10 = acc[f][2] + b0, o11 = acc[f][3] + b1;
        if (out_relu) {
            o00 = fmaxf(o00, 0.f); o01 = fmaxf(o01, 0.f);
            o10 = fmaxf(o10, 0.f); o11 = fmaxf(o11, 0.f);
        }
        if (r0 < NN) {
            *(float2*)&out[(long long)r0 * HD + n] = make_float2(o00, o01);
        }
        if (r1 < NN) {
            *(float2*)&out[(long long)r1 * HD + n] = make_float2(o10, o11);
        }
    }
}

// ---------------- BN column stats (into slot) ----------------
__global__ __launch_bounds__(256) void stats_kernel(const float* __restrict__ x,
                                                    int slot) {
    __shared__ float ss[256], sq[256];
    float* st = g_stats + slot * 2 * HD;
    int tid = threadIdx.x;
    int col = tid & 127;
    int half = tid >> 7;
    int r0 = blockIdx.x * 128 + half * 64;
    float s = 0.f, q = 0.f;
    for (int i = 0; i < 64; i++) {
        int r = r0 + i;
        if (r < NN) {
            float v = x[(long long)r * HD + col];
            s += v;
            q += v * v;
        }
    }
    ss[tid] = s; sq[tid] = q;
    __syncthreads();
    if (half == 0) {
        s += ss[tid + 128];
        q += sq[tid + 128];
        atomicAdd(&st[col], s);
        atomicAdd(&st[HD + col], q);
    }
}

// ---------------- finalize BN stats -> slot scale/shift ------------
__global__ void finalize_stats_kernel(const float* __restrict__ gamma,
                                      const float* __restrict__ beta, int slot)
{
    int c = threadIdx.x;
    const float* st = g_stats + slot * 2 * HD;
    const float inv = 1.0f / (float)NN;
    float mean = st[c] * inv;
    float var = st[HD + c] * inv - mean * mean;
    float sc = gamma[c] * rsqrtf(var + BN_EPS);
    g_scale[slot * HD + c] = sc;
    g_shift[slot * HD + c] = beta[c] - mean * sc;
}

// ---------------- per-graph readout (graph_ids sorted) --------------------
__global__ __launch_bounds__(256) void readout_kernel(const int* __restrict__ gids)
{
    int c = threadIdx.x;
    const float* h = (c < HD) ? g_enc0 : g_enc1;
    int cc = c & (HD - 1);
    int n0 = blockIdx.x * 128;
    int n1 = n0 + 128;
    if (n1 > NN) n1 = NN;
    int cur = gids[n0];
    float acc = 0.f;
    for (int n = n0; n < n1; n++) {
        int g = gids[n];
        if (g != cur) {
            atomicAdd(&g_hg[cur * 2 * HD + c], acc);
            acc = 0.f;
            cur = g;
        }
        acc += h[(long long)n * HD + cc];
    }
    atomicAdd(&g_hg[cur * 2 * HD + c], acc);
}

// ---------------- output MLP ----------------
__global__ void mlp1_kernel(const float* __restrict__ W, const float* __restrict__ b)
{
    __shared__ float row[2 * HD];
    int g = blockIdx.x, c = threadIdx.x;
    row[c] = g_hg[g * 2 * HD + c];
    row[c + HD] = g_hg[g * 2 * HD + c + HD];
    __syncthreads();
    float acc = b[c];
#pragma unroll 4
    for (int k = 0; k < 2 * HD; k++) acc = fmaf(row[k], W[k * HD + c], acc);
    g_m1[g * HD + c] = fmaxf(acc, 0.f);
}

__global__ void mlp2_kernel(const float* __restrict__ W, const float* __restrict__ b)
{
    __shared__ float row[HD];
    int g = blockIdx.x, c = threadIdx.x;
    row[c] = g_m1[g * HD + c];
    __syncthreads();
    float acc = b[c];
#pragma unroll 4
    for (int k = 0; k < HD; k++) acc = fmaf(row[k], W[k * HD + c], acc);
    g_m2[g * HD + c] = fmaxf(acc, 0.f);
}

__global__ void mlp3_kernel(const float* __restrict__ W, const float* __restrict__ b,
                            float* __restrict__ out)
{
    int g = threadIdx.x;
    if (g < NG) {
        float acc = b[0];
#pragma unroll 4
        for (int k = 0; k < HD; k++) acc = fmaf(g_m2[g * HD + k], W[k], acc);
        out[g] = acc;
    }
}

// ---------------- launch ----------------
extern "C" void kernel_launch(void* const* d_in, const int* in_sizes, int n_in,
                              void* d_out, int out_size)
{
    const float* feats = (const float*)d_in[0];
    const int* src = (const int*)d_in[1];
    const int* dst = (const int*)d_in[2];
    const int* gids = (const int*)d_in[3];
    const float* eps = (const float*)d_in[5];
    const float* Wa = (const float*)d_in[6];
    const float* ba = (const float*)d_in[7];
    const float* bng = (const float*)d_in[8];
    const float* bnb = (const float*)d_in[9];
    const float* Wb = (const float*)d_in[10];
    const float* bb = (const float*)d_in[11];
    const float* oW1 = (const float*)d_in[12];
    const float* ob1 = (const float*)d_in[13];
    const float* oW2 = (const float*)d_in[14];
    const float* ob2 = (const float*)d_in[15];
    const float* oW3 = (const float*)d_in[16];
    const float* ob3 = (const float*)d_in[17];
    float* out = (float*)d_out;

    cudaFuncSetAttribute(gemm_mma_kernel,
                         cudaFuncAttributeMaxDynamicSharedMemorySize, GSM_TOTAL);

    // side stream + fork/join events (created once; resources, not state)
    static cudaStream_t s1 = [] { cudaStream_t s; cudaStreamCreate(&s); return s; }();
    static cudaEvent_t evF = [] {
        cudaEvent_t e; cudaEventCreateWithFlags(&e, cudaEventDisableTiming); return e; }();
    static cudaEvent_t evJ = [] {
        cudaEvent_t e; cudaEventCreateWithFlags(&e, cudaEventDisableTiming); return e; }();

    float *agg0p, *agg1p, *x0p, *x1p, *buf0p, *buf1p, *e0p, *e1p, *hgp;
    cudaGetSymbolAddress((void**)&agg0p, g_agg0);
    cudaGetSymbolAddress((void**)&agg1p, g_agg1);
    cudaGetSymbolAddress((void**)&x0p, g_x0);
    cudaGetSymbolAddress((void**)&x1p, g_x1);
    cudaGetSymbolAddress((void**)&buf0p, g_buf0);
    cudaGetSymbolAddress((void**)&buf1p, g_buf1);
    cudaGetSymbolAddress((void**)&e0p, g_enc0);
    cudaGetSymbolAddress((void**)&e1p, g_enc1);
    cudaGetSymbolAddress((void**)&hgp, g_hg);
    int *ei0p, *ei1p, *degp, *rsp;
    cudaGetSymbolAddress((void**)&ei0p, g_eidx0);
    cudaGetSymbolAddress((void**)&ei1p, g_eidx1);
    cudaGetSymbolAddress((void**)&degp, g_deg);
    cudaGetSymbolAddress((void**)&rsp, g_rowstart);

    const int gemm_blocks = (NN + 127) / 128;        // 391
    const int edge2_blocks = (2 * NE + 255) / 256;   // 6250
    const int agg_blocks = (NN * 32 + 255) / 256;    // 6250

    // Prep + CSR on the main stream
    prep_kernel<<<(8 * HD * HD + 255) / 256, 256>>>(Wa, Wb);
    cudaMemsetAsync(degp, 0, 2 * NN * sizeof(int));
    deg2_kernel<<<edge2_blocks, 256>>>(dst);
    scan2_kernel<<<2, 1024>>>();
    scatter2_kernel<<<edge2_blocks, 256>>>(src, dst);

    // fork: encoder 1 chain runs on s1, encoder 0 chain on the main stream
    cudaEventRecord(evF, 0);
    cudaStreamWaitEvent(s1, evF, 0);

    for (int e = 0; e < 2; e++) {
        cudaStream_t st = e ? s1 : (cudaStream_t)0;
        int* eidx = e ? ei1p : ei0p;
        const int* rowstart = rsp + e * (NN + 1);
        float* aggp = e ? agg1p : agg0p;
        float* xp = e ? x1p : x0p;
        float* bufp = e ? buf1p : buf0p;
        float* enc = e ? e1p : e0p;
        const float* hin = feats;
        for (int l = 0; l < 2; l++) {
            int wl = e * 2 + l;
            agg_csr_kernel<<<agg_blocks, 256, 0, st>>>(hin, rowstart, eidx,
                                                       eps + wl, aggp);
            gemm_mma_kernel<<<gemm_blocks, 256, GSM_TOTAL, st>>>(
                aggp, ba + wl * HD, xp, wl, -1, 0);
            stats_kernel<<<gemm_blocks, 256, 0, st>>>(xp, wl);
            finalize_stats_kernel<<<1, HD, 0, st>>>(bng + wl * HD, bnb + wl * HD, wl);
            float* o = (l == 0) ? bufp : enc;
            gemm_mma_kernel<<<gemm_blocks, 256, GSM_TOTAL, st>>>(
                xp, bb + wl * HD, o, 4 + wl, wl, (l == 0) ? 1 : 0);
            hin = bufp;
        }
    }

    // join
    cudaEventRecord(evJ, s1);
    cudaStreamWaitEvent((cudaStream_t)0, evJ, 0);

    cudaMemsetAsync(hgp, 0, NG * 2 * HD * sizeof(float));
    readout_kernel<<<(NN + 127) / 128, 256>>>(gids);
    mlp1_kernel<<<NG, HD>>>(oW1, ob1);
    mlp2_kernel<<<NG, HD>>>(oW2, ob2);
    mlp3_kernel<<<1, NG>>>(oW3, ob3, out);
}

// round 11
// speedup vs baseline: 1.5707x; 1.1354x over previous
#include <cuda_runtime.h>
#include <cuda_bf16.h>
#include <math.h>
#include <stdint.h>

#define NN 50000
#define NE 800000
#define NG 256
#define HD 128
#define BN_EPS 1e-5f

// ---------------- device scratch (no allocation allowed) ----------------
__device__ float g_agg0[NN * HD];
__device__ float g_agg1[NN * HD];
__device__ float g_x0[NN * HD];
__device__ float g_x1[NN * HD];
__device__ float g_buf0[NN * HD];
__device__ float g_buf1[NN * HD];
__device__ float g_enc0[NN * HD];
__device__ float g_enc1[NN * HD];
__device__ float g_stats[4 * 2 * HD];        // 4 slots x (sum[128], sq[128])
__device__ __nv_bfloat16 g_wt_hi[8 * HD * HD];   // 8 slots, W^T hi [n][k]
__device__ __nv_bfloat16 g_wt_lo[8 * HD * HD];
// CSR scratch (both edge types)
__device__ int g_deg[2 * NN];
__device__ int g_rowstart[2 * (NN + 1)];
__device__ int g_cursor[2 * NN];
__device__ int g_eidx0[NE];
__device__ int g_eidx1[NE];

// ---------------- CSR build (per edge-type, stream-parallel) --------------
__global__ __launch_bounds__(256) void deg_e_kernel(const int* __restrict__ dst,
                                                    int e) {
    int i = blockIdx.x * blockDim.x + threadIdx.x;
    if (i < NE) atomicAdd(&g_deg[e * NN + dst[i]], 1);
}

__global__ __launch_bounds__(1024) void scan_e_kernel(int e) {
    __shared__ int ssum[1024];
    int* deg = g_deg + e * NN;
    int* rowstart = g_rowstart + e * (NN + 1);
    int* cursor = g_cursor + e * NN;
    int t = threadIdx.x;
    const int CH = (NN + 1023) / 1024;
    int start = t * CH;
    int end = start + CH; if (end > NN) end = NN;
    if (start > NN) start = NN;
    int s = 0;
    for (int i = start; i < end; i++) s += deg[i];
    ssum[t] = s;
    __syncthreads();
    for (int off = 1; off < 1024; off <<= 1) {
        int v = (t >= off) ? ssum[t - off] : 0;
        __syncthreads();
        ssum[t] += v;
        __syncthreads();
    }
    int base = (t == 0) ? 0 : ssum[t - 1];
    for (int i = start; i < end; i++) {
        int d = deg[i];
        rowstart[i] = base;
        cursor[i] = base;
        base += d;
    }
    if (t == 1023) rowstart[NN] = base;
}

__global__ __launch_bounds__(256) void scatter_e_kernel(
    const int* __restrict__ src, const int* __restrict__ dst,
    int* __restrict__ eidx, int e)
{
    int i = blockIdx.x * blockDim.x + threadIdx.x;
    if (i < NE) {
        int p = atomicAdd(&g_cursor[e * NN + dst[i]], 1);
        eidx[p] = src[i];
    }
}

// -------- CSR aggregation ----
__global__ __launch_bounds__(256) void agg_csr_kernel(
    const float* __restrict__ h, const int* __restrict__ rowstart,
    const int* __restrict__ eidx,
    const float* __restrict__ eps_ptr, float* __restrict__ xout)
{
    int warp = (blockIdx.x * 256 + threadIdx.x) >> 5;
    int lane = threadIdx.x & 31;
    if (warp >= NN) return;
    int ro = rowstart[warp];
    int re = rowstart[warp + 1];
    float eps1 = 1.0f + eps_ptr[0];
    float4 hv = ((const float4*)h)[(long long)warp * 32 + lane];
    float4 acc = make_float4(eps1 * hv.x, eps1 * hv.y, eps1 * hv.z, eps1 * hv.w);
    int j = ro;
    for (; j + 4 <= re; j += 4) {
        int s0 = eidx[j], s1 = eidx[j + 1], s2 = eidx[j + 2], s3 = eidx[j + 3];
        float4 v0 = ((const float4*)h)[(long long)s0 * 32 + lane];
        float4 v1 = ((const float4*)h)[(long long)s1 * 32 + lane];
        float4 v2 = ((const float4*)h)[(long long)s2 * 32 + lane];
        float4 v3 = ((const float4*)h)[(long long)s3 * 32 + lane];
        acc.x += v0.x + v1.x + v2.x + v3.x;
        acc.y += v0.y + v1.y + v2.y + v3.y;
        acc.z += v0.z + v1.z + v2.z + v3.z;
        acc.w += v0.w + v1.w + v2.w + v3.w;
    }
    for (; j < re; j++) {
        int s = eidx[j];
        float4 v = ((const float4*)h)[(long long)s * 32 + lane];
        acc.x += v.x; acc.y += v.y; acc.z += v.z; acc.w += v.w;
    }
    ((float4*)xout)[(long long)warp * 32 + lane] = acc;
}

// ================= mma.sync bf16 GEMM machinery =================
#define GSM_TOTAL 131072

__device__ __forceinline__ uint32_t smem_u32(const void* p) {
    uint32_t a;
    asm("{ .reg .u64 t; cvta.to.shared.u64 t, %1; cvt.u32.u64 %0, t; }"
        : "=r"(a) : "l"(p));
    return a;
}
__device__ __forceinline__ uint32_t swz(int row, int k) {
    return (uint32_t)(row * 256 + ((((k >> 3) ^ (row & 7)) & 15) << 4) + (k & 7) * 2);
}
__device__ __forceinline__ unsigned int pack_bf2(float lo, float hi) {
    unsigned int r;
    asm("cvt.rn.bf16x2.f32 %0, %1, %2;" : "=r"(r) : "f"(hi), "f"(lo));
    return r;
}
__device__ __forceinline__ void ldm4(uint32_t* r, uint32_t addr) {
    asm volatile("ldmatrix.sync.aligned.m8n8.x4.shared.b16 {%0,%1,%2,%3}, [%4];"
        : "=r"(r[0]), "=r"(r[1]), "=r"(r[2]), "=r"(r[3]) : "r"(addr));
}
__device__ __forceinline__ void mma16816(float* d, const uint32_t* a,
                                         uint32_t b0, uint32_t b1) {
    asm volatile(
        "mma.sync.aligned.m16n8k16.row.col.f32.bf16.bf16.f32 "
        "{%0,%1,%2,%3}, {%4,%5,%6,%7}, {%8,%9}, {%0,%1,%2,%3};"
        : "+f"(d[0]), "+f"(d[1]), "+f"(d[2]), "+f"(d[3])
        : "r"(a[0]), "r"(a[1]), "r"(a[2]), "r"(a[3]), "r"(b0), "r"(b1));
}

// ---------------- prep: split all 8 weights to bf16 hi/lo + zero stats ----
__global__ __launch_bounds__(256) void prep_kernel(
    const float* __restrict__ Wa, const float* __restrict__ Wb)
{
    int idx = blockIdx.x * 256 + threadIdx.x;
    if (idx < 8 * HD * HD) {
        int slot = idx >> 14;
        int m = idx & 16383;
        int k = m >> 7, n = m & 127;
        const float* W = (slot < 4) ? (Wa + slot * HD * HD)
                                    : (Wb + (slot - 4) * HD * HD);
        float v = W[k * HD + n];
        __nv_bfloat16 h = __float2bfloat16(v);
        float r = v - __bfloat162float(h);
        g_wt_hi[slot * HD * HD + n * HD + k] = h;
        g_wt_lo[slot * HD * HD + n * HD + k] = __float2bfloat16(r);
    }
    if (idx < 4 * 2 * HD) g_stats[idx] = 0.f;
}

// ---------------- mma GEMM: out = act(xin') @ W + b ------------------
// bn_slot >= 0: xin' = relu(BN(xin)); scale/shift computed in-kernel from
// g_stats[bn_slot] + gamma/beta.
__global__ __launch_bounds__(256, 1) void gemm_mma_kernel(
    const float* __restrict__ xin, const float* __restrict__ bias,
    float* __restrict__ out, int wslot, int bn_slot, int out_relu,
    const float* __restrict__ gamma, const float* __restrict__ beta)
{
    extern __shared__ char smem[];
    __shared__ float sbias[HD];
    __shared__ float sscale[HD];
    __shared__ float sshift[HD];
    uint32_t sb = smem_u32(smem);
    int tid = threadIdx.x;
    int row0 = blockIdx.x * 128;

    if (tid < HD) {
        sbias[tid] = bias[tid];
        if (bn_slot >= 0) {
            const float* st = g_stats + bn_slot * 2 * HD;
            const float inv = 1.0f / (float)NN;
            float mean = st[tid] * inv;
            float var = st[HD + tid] * inv - mean * mean;
            float sc = gamma[tid] * rsqrtf(var + BN_EPS);
            sscale[tid] = sc;
            sshift[tid] = beta[tid] - mean * sc;
        }
    }
    __syncthreads();

    // ---- stage A (hi/lo split, swizzled) ----
#pragma unroll
    for (int it = 0; it < 8; it++) {
        int idx = tid + it * 256;
        int row = idx >> 4;
        int k0 = (idx & 15) * 8;
        int grow = row0 + row;
        float f[8];
        if (grow < NN) {
            float4 v0 = *(const float4*)&xin[(long long)grow * HD + k0];
            float4 v1 = *(const float4*)&xin[(long long)grow * HD + k0 + 4];
            f[0] = v0.x; f[1] = v0.y; f[2] = v0.z; f[3] = v0.w;
            f[4] = v1.x; f[5] = v1.y; f[6] = v1.z; f[7] = v1.w;
            if (bn_slot >= 0) {
#pragma unroll
                for (int i = 0; i < 8; i++)
                    f[i] = fmaxf(f[i] * sscale[k0 + i] + sshift[k0 + i], 0.f);
            }
        } else {
#pragma unroll
            for (int i = 0; i < 8; i++) f[i] = 0.f;
        }
        float hi[8], lo[8];
#pragma unroll
        for (int i = 0; i < 8; i++) {
            hi[i] = __bfloat162float(__float2bfloat16(f[i]));
            lo[i] = f[i] - hi[i];
        }
        uint4 hv = make_uint4(pack_bf2(hi[0], hi[1]), pack_bf2(hi[2], hi[3]),
                              pack_bf2(hi[4], hi[5]), pack_bf2(hi[6], hi[7]));
        uint4 lv = make_uint4(pack_bf2(lo[0], lo[1]), pack_bf2(lo[2], lo[3]),
                              pack_bf2(lo[4], lo[5]), pack_bf2(lo[6], lo[7]));
        uint32_t off = swz(row, k0);
        *(uint4*)(smem + off) = hv;
        *(uint4*)(smem + 32768 + off) = lv;
    }
    // ---- stage B from preconverted slot ----
    const __nv_bfloat16* wh = g_wt_hi + wslot * HD * HD;
    const __nv_bfloat16* wl_ = g_wt_lo + wslot * HD * HD;
#pragma unroll
    for (int it = 0; it < 8; it++) {
        int idx = tid + it * 256;
        int row = idx >> 4;
        int k0 = (idx & 15) * 8;
        uint4 hv = *(const uint4*)&wh[row * HD + k0];
        uint4 lv = *(const uint4*)&wl_[row * HD + k0];
        uint32_t off = swz(row, k0);
        *(uint4*)(smem + 65536 + off) = hv;
        *(uint4*)(smem + 98304 + off) = lv;
    }
    __syncthreads();

    // ---- mainloop: warp w owns rows 16w..16w+15, all 128 cols ----
    int w = tid >> 5, l = tid & 31;
    float acc[16][4];
#pragma unroll
    for (int f = 0; f < 16; f++)
#pragma unroll
        for (int q = 0; q < 4; q++) acc[f][q] = 0.f;

    int rowA = 16 * w + ((l >> 3) & 1) * 8 + (l & 7);
    int aKoff = (l >> 4) * 8;
    int bRowL = ((l >> 4) << 3) + (l & 7);
    int bKoff = ((l >> 3) & 1) * 8;

#pragma unroll
    for (int ks = 0; ks < 8; ks++) {
        int k0 = ks * 16;
        uint32_t ah[4], al[4];
        uint32_t aaddr = sb + swz(rowA, k0 + aKoff);
        ldm4(ah, aaddr);
        ldm4(al, aaddr + 32768);
#pragma unroll
        for (int fg = 0; fg < 8; fg++) {
            uint32_t bh[4], bl[4];
            uint32_t baddr = sb + 65536 + swz(16 * fg + bRowL, k0 + bKoff);
            ldm4(bh, baddr);
            ldm4(bl, baddr + 32768);
            mma16816(acc[2 * fg], ah, bh[0], bh[1]);
            mma16816(acc[2 * fg], al, bh[0], bh[1]);
            mma16816(acc[2 * fg], ah, bl[0], bl[1]);
            mma16816(acc[2 * fg + 1], ah, bh[2], bh[3]);
            mma16816(acc[2 * fg + 1], al, bh[2], bh[3]);
            mma16816(acc[2 * fg + 1], ah, bl[2], bl[3]);
        }
    }

    // ---- epilogue: bias (+relu), store ----
    int g = l >> 2, t4 = l & 3;
    int r0 = row0 + 16 * w + g;
    int r1 = r0 + 8;
#pragma unroll
    for (int f = 0; f < 16; f++) {
        int n = 8 * f + 2 * t4;
        float b0 = sbias[n], b1 = sbias[n + 1];
        float o00 = acc[f][0] + b0, o01 = acc[f][1] + b1;
        float o10 = acc[f][2] + b0, o11 = acc[f][3] + b1;
        if (out_relu) {
            o00 = fmaxf(o00, 0.f); o01 = fmaxf(o01, 0.f);
            o10 = fmaxf(o10, 0.f); o11 = fmaxf(o11, 0.f);
        }
        if (r0 < NN) {
            *(float2*)&out[(long long)r0 * HD + n] = make_float2(o00, o01);
        }
        if (r1 < NN) {
            *(float2*)&out[(long long)r1 * HD + n] = make_float2(o10, o11);
        }
    }
}

// ---------------- BN column stats (into slot) ----------------
__global__ __launch_bounds__(256) void stats_kernel(const float* __restrict__ x,
                                                    int slot) {
    __shared__ float ss[256], sq[256];
    float* st = g_stats + slot * 2 * HD;
    int tid = threadIdx.x;
    int col = tid & 127;
    int half = tid >> 7;
    int r0 = blockIdx.x * 128 + half * 64;
    float s = 0.f, q = 0.f;
    for (int i = 0; i < 64; i++) {
        int r = r0 + i;
        if (r < NN) {
            float v = x[(long long)r * HD + col];
            s += v;
            q += v * v;
        }
    }
    ss[tid] = s; sq[tid] = q;
    __syncthreads();
    if (half == 0) {
        s += ss[tid + 128];
        q += sq[tid + 128];
        atomicAdd(&st[col], s);
        atomicAdd(&st[HD + col], q);
    }
}

// -------- fused readout + 3-layer MLP: one block per graph ----------------
__global__ __launch_bounds__(256) void readout_mlp_kernel(
    const int* __restrict__ gids,
    const float* __restrict__ oW1, const float* __restrict__ ob1,
    const float* __restrict__ oW2, const float* __restrict__ ob2,
    const float* __restrict__ oW3, const float* __restrict__ ob3,
    float* __restrict__ out)
{
    __shared__ float row[2 * HD];
    __shared__ float m1[HD];
    __shared__ float m2[HD];
    int g = blockIdx.x;
    int c = threadIdx.x;

    // binary search node range of graph g in sorted gids
    int lo = 0, hi = NN;
    while (lo < hi) { int mid = (lo + hi) >> 1; if (gids[mid] < g) lo = mid + 1; else hi = mid; }
    int start = lo;
    hi = NN;
    while (lo < hi) { int mid = (lo + hi) >> 1; if (gids[mid] < g + 1) lo = mid + 1; else hi = mid; }
    int end = lo;

    const float* h = (c < HD) ? g_enc0 : g_enc1;
    int cc = c & (HD - 1);
    float acc = 0.f;
    for (int n = start; n < end; n++) acc += h[(long long)n * HD + cc];
    row[c] = acc;
    __syncthreads();

    if (c < HD) {
        float a = ob1[c];
#pragma unroll 4
        for (int k = 0; k < 2 * HD; k++) a = fmaf(row[k], oW1[k * HD + c], a);
        m1[c] = fmaxf(a, 0.f);
    }
    __syncthreads();
    if (c < HD) {
        float a = ob2[c];
#pragma unroll 4
        for (int k = 0; k < HD; k++) a = fmaf(m1[k], oW2[k * HD + c], a);
        m2[c] = fmaxf(a, 0.f);
    }
    __syncthreads();
    if (c < 32) {
        float a = 0.f;
        for (int k = c; k < HD; k += 32) a = fmaf(m2[k], oW3[k], a);
#pragma unroll
        for (int m = 16; m; m >>= 1) a += __shfl_xor_sync(0xFFFFFFFFu, a, m);
        if (c == 0) out[g] = a + ob3[0];
    }
}

// ---------------- launch ----------------
extern "C" void kernel_launch(void* const* d_in, const int* in_sizes, int n_in,
                              void* d_out, int out_size)
{
    const float* feats = (const float*)d_in[0];
    const int* src = (const int*)d_in[1];
    const int* dst = (const int*)d_in[2];
    const int* gids = (const int*)d_in[3];
    const float* eps = (const float*)d_in[5];
    const float* Wa = (const float*)d_in[6];
    const float* ba = (const float*)d_in[7];
    const float* bng = (const float*)d_in[8];
    const float* bnb = (const float*)d_in[9];
    const float* Wb = (const float*)d_in[10];
    const float* bb = (const float*)d_in[11];
    const float* oW1 = (const float*)d_in[12];
    const float* ob1 = (const float*)d_in[13];
    const float* oW2 = (const float*)d_in[14];
    const float* ob2 = (const float*)d_in[15];
    const float* oW3 = (const float*)d_in[16];
    const float* ob3 = (const float*)d_in[17];
    float* out = (float*)d_out;

    cudaFuncSetAttribute(gemm_mma_kernel,
                         cudaFuncAttributeMaxDynamicSharedMemorySize, GSM_TOTAL);

    static cudaStream_t s1 = [] { cudaStream_t s; cudaStreamCreate(&s); return s; }();
    static cudaEvent_t evF = [] {
        cudaEvent_t e; cudaEventCreateWithFlags(&e, cudaEventDisableTiming); return e; }();
    static cudaEvent_t evJ = [] {
        cudaEvent_t e; cudaEventCreateWithFlags(&e, cudaEventDisableTiming); return e; }();

    float *agg0p, *agg1p, *x0p, *x1p, *buf0p, *buf1p, *e0p, *e1p;
    cudaGetSymbolAddress((void**)&agg0p, g_agg0);
    cudaGetSymbolAddress((void**)&agg1p, g_agg1);
    cudaGetSymbolAddress((void**)&x0p, g_x0);
    cudaGetSymbolAddress((void**)&x1p, g_x1);
    cudaGetSymbolAddress((void**)&buf0p, g_buf0);
    cudaGetSymbolAddress((void**)&buf1p, g_buf1);
    cudaGetSymbolAddress((void**)&e0p, g_enc0);
    cudaGetSymbolAddress((void**)&e1p, g_enc1);
    int *ei0p, *ei1p, *degp, *rsp;
    cudaGetSymbolAddress((void**)&ei0p, g_eidx0);
    cudaGetSymbolAddress((void**)&ei1p, g_eidx1);
    cudaGetSymbolAddress((void**)&degp, g_deg);
    cudaGetSymbolAddress((void**)&rsp, g_rowstart);

    const int gemm_blocks = (NN + 127) / 128;        // 391
    const int edge_blocks = (NE + 255) / 256;        // 3125
    const int agg_blocks = (NN * 32 + 255) / 256;    // 6250

    // serial head: weight split + stats zero + deg zero, then fork
    prep_kernel<<<(8 * HD * HD + 255) / 256, 256>>>(Wa, Wb);
    cudaMemsetAsync(degp, 0, 2 * NN * sizeof(int));
    cudaEventRecord(evF, 0);
    cudaStreamWaitEvent(s1, evF, 0);

    for (int e = 0; e < 2; e++) {
        cudaStream_t st = e ? s1 : (cudaStream_t)0;
        int* eidx = e ? ei1p : ei0p;
        const int* rowstart = rsp + e * (NN + 1);
        float* aggp = e ? agg1p : agg0p;
        float* xp = e ? x1p : x0p;
        float* bufp = e ? buf1p : buf0p;
        float* enc = e ? e1p : e0p;

        // per-encoder CSR build on its own stream
        deg_e_kernel<<<edge_blocks, 256, 0, st>>>(dst + (long long)e * NE, e);
        scan_e_kernel<<<1, 1024, 0, st>>>(e);
        scatter_e_kernel<<<edge_blocks, 256, 0, st>>>(
            src + (long long)e * NE, dst + (long long)e * NE, eidx, e);

        const float* hin = feats;
        for (int l = 0; l < 2; l++) {
            int wl = e * 2 + l;
            agg_csr_kernel<<<agg_blocks, 256, 0, st>>>(hin, rowstart, eidx,
                                                       eps + wl, aggp);
            gemm_mma_kernel<<<gemm_blocks, 256, GSM_TOTAL, st>>>(
                aggp, ba + wl * HD, xp, wl, -1, 0, (const float*)0, (const float*)0);
            stats_kernel<<<gemm_blocks, 256, 0, st>>>(xp, wl);
            float* o = (l == 0) ? bufp : enc;
            gemm_mma_kernel<<<gemm_blocks, 256, GSM_TOTAL, st>>>(
                xp, bb + wl * HD, o, 4 + wl, wl, (l == 0) ? 1 : 0,
                bng + wl * HD, bnb + wl * HD);
            hin = bufp;
        }
    }

    // join + fused tail
    cudaEventRecord(evJ, s1);
    cudaStreamWaitEvent((cudaStream_t)0, evJ, 0);
    readout_mlp_kernel<<<NG, 256>>>(gids, oW1, ob1, oW2, ob2, oW3, ob3, out);
}